// round 15
// baseline (speedup 1.0000x reference)
#include <cuda_runtime.h>

#define M_        8
#define E_        256
#define H_        256
#define L_        16384
#define NPOS      1024          // 32*32
#define NSPECIAL_ 32
#define SIDX_     8
#define NPLAYERS_ 4
#define POL_STRIDE (L_ + SIDX_) // 16392
#define NCHUNK    8             // e-chunks per head in stage 1
#define ECHUNK    (E_ / NCHUNK) // 32

// device scratch (no cudaMalloc allowed)
__device__ float g_tab[M_ * NPOS * 2];               // [m][p][k]       64 KB
__device__ float g_clsdot[M_];                       // cls part of policy dot (+bp)
__device__ float g_part[2 * NCHUNK * M_ * H_];       // [head][chunk][m][j]  128 KB

// ---------------------------------------------------------------------------
// Launch 1: grid = 1024 (table) + 16 (mlp stage1 partials) + 1 (cls_dot)
// ---------------------------------------------------------------------------
__global__ void __launch_bounds__(256)
fused_kernel(const float* __restrict__ emb,
             const float* __restrict__ cls,
             const float* __restrict__ Wp,
             const float* __restrict__ bp,
             const float* __restrict__ Ws1,
             const float* __restrict__ Wv1)
{
    __shared__ float sh[M_ * E_];       // 8 KB, reused per role
    const int tid = threadIdx.x;
    const int bx  = blockIdx.x;

    if (bx < 1024) {
        // ---- per-position dot table: warp per (m,p), reads embedding once ----
        float4* sh_wp = (float4*)sh;    // Wp[0:512] as 128 float4
        if (tid < 128) sh_wp[tid] = ((const float4*)Wp)[tid];
        __syncthreads();

        const int w    = bx * 8 + (tid >> 5);
        const int m    = w >> 10;
        const int p    = w & (NPOS - 1);
        const int lane = tid & 31;

        const float4* row = (const float4*)(emb + ((size_t)(m * NPOS + p)) * E_);

        float a0 = 0.f, a1 = 0.f;
        float4 v  = row[lane];
        float4 wa = sh_wp[lane];
        float4 wb = sh_wp[64 + lane];
        a0 += v.x*wa.x + v.y*wa.y + v.z*wa.z + v.w*wa.w;
        a1 += v.x*wb.x + v.y*wb.y + v.z*wb.z + v.w*wb.w;
        v  = row[lane + 32];
        wa = sh_wp[lane + 32];
        wb = sh_wp[96 + lane];
        a0 += v.x*wa.x + v.y*wa.y + v.z*wa.z + v.w*wa.w;
        a1 += v.x*wb.x + v.y*wb.y + v.z*wb.z + v.w*wb.w;

        #pragma unroll
        for (int o = 16; o; o >>= 1) {
            a0 += __shfl_xor_sync(0xffffffffu, a0, o);
            a1 += __shfl_xor_sync(0xffffffffu, a1, o);
        }
        if (lane == 0)
            ((float2*)g_tab)[m * NPOS + p] = make_float2(a0, a1);
    }
    else if (bx < 1024 + 16) {
        // ---- MLP stage 1: partial h over one e-chunk of one head ----
        const int idx   = bx - 1024;
        const int head  = idx >> 3;          // 0=special(Ws1), 1=value(Wv1)
        const int chunk = idx & 7;
        const float* __restrict__ W1 = head ? Wv1 : Ws1;

        for (int i = tid; i < M_ * E_; i += 256) sh[i] = cls[i];
        __syncthreads();

        const int e0 = chunk * ECHUNK;
        float acc[M_];
        #pragma unroll
        for (int m = 0; m < M_; m++) acc[m] = 0.f;

        #pragma unroll 8
        for (int ee = 0; ee < ECHUNK; ee++) {
            const float wv = __ldg(&W1[(e0 + ee) * H_ + tid]);
            #pragma unroll
            for (int m = 0; m < M_; m++) acc[m] += sh[m * E_ + e0 + ee] * wv;
        }

        float* dst = g_part + ((head * NCHUNK + chunk) * M_) * H_;
        #pragma unroll
        for (int m = 0; m < M_; m++) dst[m * H_ + tid] = acc[m];
    }
    else {
        // ---- cls_dot: warp per m ----
        for (int i = tid; i < M_ * E_; i += 256) sh[i] = cls[i];
        __syncthreads();
        const int w = tid >> 5, lane = tid & 31;
        float a = 0.f;
        for (int e = lane; e < E_; e += 32)
            a += sh[w * E_ + e] * __ldg(&Wp[2 * E_ + e]);
        #pragma unroll
        for (int o = 16; o; o >>= 1) a += __shfl_xor_sync(0xffffffffu, a, o);
        if (lane == 0) g_clsdot[w] = a + __ldg(bp);
    }
}

// ---------------------------------------------------------------------------
// Launch 2: grid = 128 (policy fill, 4 elems/thread) + 2 (head finish).
//   Smem <= ~9 KB in all branches (warp-limited residency, 8 CTAs/SM).
//   Table split into two planes (k=0 / k=1) so gathers use all 32 banks.
// ---------------------------------------------------------------------------
__global__ void __launch_bounds__(256)
finish_kernel(const int*   __restrict__ sel,
              const int*   __restrict__ sidx,
              const float* __restrict__ bv1,
              const float* __restrict__ Wv2, const float* __restrict__ bv2,
              const float* __restrict__ bs1,
              const float* __restrict__ Ws2, const float* __restrict__ bs2,
              float* __restrict__ out)
{
    const int tid = threadIdx.x;
    const int bx  = blockIdx.x;

    if (bx < 128) {
        // ---- policy fill: 16 blocks per m, 1024 l per block ----
        __shared__ float tab0[NPOS];   // k=0 plane, 4 KB
        __shared__ float tab1[NPOS];   // k=1 plane, 4 KB
        __shared__ float sh_cd;
        const int m     = bx >> 4;
        const int lbase = (bx & 15) * 1024;

        // stage + deinterleave: float4 = {tab[p].k0, tab[p].k1, tab[p+1].k0, tab[p+1].k1}
        const float4* src = (const float4*)(g_tab + m * NPOS * 2);
        {
            float4 v0 = src[tid];
            float4 v1 = src[256 + tid];
            const int p0 = tid * 2, p1 = 512 + tid * 2;
            tab0[p0]     = v0.x;  tab1[p0]     = v0.y;
            tab0[p0 + 1] = v0.z;  tab1[p0 + 1] = v0.w;
            tab0[p1]     = v1.x;  tab1[p1]     = v1.y;
            tab0[p1 + 1] = v1.z;  tab1[p1 + 1] = v1.w;
        }
        if (tid == 0) sh_cd = g_clsdot[m];
        __syncthreads();

        const int l0 = lbase + tid * 4;
        const int4* sp = (const int4*)sel;   // {r0,c0,r1,c1} per l
        const int4 a = sp[l0];
        const int4 b = sp[l0 + 1];
        const int4 c = sp[l0 + 2];
        const int4 d = sp[l0 + 3];

        float4 r;
        r.x = tab0[(a.x << 5) | a.y] + tab1[(a.z << 5) | a.w] + sh_cd;
        r.y = tab0[(b.x << 5) | b.y] + tab1[(b.z << 5) | b.w] + sh_cd;
        r.z = tab0[(c.x << 5) | c.y] + tab1[(c.z << 5) | c.w] + sh_cd;
        r.w = tab0[(d.x << 5) | d.y] + tab1[(d.z << 5) | d.w] + sh_cd;

        *(float4*)(out + m * POL_STRIDE + l0) = r;
    } else {
        // ---- head finish (2 blocks) ----
        __shared__ float sh_h[M_][H_];              // 8 KB
        __shared__ float sh_spec[M_][NSPECIAL_];    // 1 KB
        const int head = bx - 128;                  // 0=special, 1=value

        // hidden = relu(bias + sum of partials); thread owns column j = tid
        const float b = head ? __ldg(&bv1[tid]) : __ldg(&bs1[tid]);
        const float* part = g_part + (head * NCHUNK * M_) * H_;
        #pragma unroll
        for (int m = 0; m < M_; m++) {
            float a = b;
            #pragma unroll
            for (int c = 0; c < NCHUNK; c++)
                a += part[(c * M_ + m) * H_ + tid];
            sh_h[m][tid] = fmaxf(a, 0.f);
        }
        __syncthreads();

        if (head == 0) {
            // special_all = h @ Ws2 + bs2 : warp m, lane s
            const int m = tid >> 5, s = tid & 31;
            float a = __ldg(&bs2[s]);
            #pragma unroll 8
            for (int j = 0; j < H_; j++)
                a += sh_h[m][j] * __ldg(&Ws2[j * NSPECIAL_ + s]);
            sh_spec[m][s] = a;
            __syncthreads();
            if (tid < M_ * SIDX_) {
                const int mm = tid / SIDX_, i = tid % SIDX_;
                out[mm * POL_STRIDE + L_ + i] = sh_spec[mm][__ldg(&sidx[i])];
            }
        } else {
            if (tid < M_ * NPLAYERS_) {
                const int m = tid / NPLAYERS_, n = tid % NPLAYERS_;
                float a = __ldg(&bv2[n]);
                #pragma unroll 8
                for (int j = 0; j < H_; j++)
                    a += sh_h[m][j] * __ldg(&Wv2[j * NPLAYERS_ + n]);
                out[M_ * POL_STRIDE + m * NPLAYERS_ + n] = a;
            }
        }
    }
}

// ---------------------------------------------------------------------------
extern "C" void kernel_launch(void* const* d_in, const int* in_sizes, int n_in,
                              void* d_out, int out_size)
{
    const float* emb  = (const float*)d_in[0];
    const float* cls  = (const float*)d_in[1];
    const int*   sel  = (const int*)  d_in[2];
    const int*   sidx = (const int*)  d_in[3];
    const float* Wp   = (const float*)d_in[4];
    const float* bp   = (const float*)d_in[5];
    const float* Wv1  = (const float*)d_in[6];
    const float* bv1  = (const float*)d_in[7];
    const float* Wv2  = (const float*)d_in[8];
    const float* bv2  = (const float*)d_in[9];
    const float* Ws1  = (const float*)d_in[10];
    const float* bs1  = (const float*)d_in[11];
    const float* Ws2  = (const float*)d_in[12];
    const float* bs2  = (const float*)d_in[13];
    float* out = (float*)d_out;

    fused_kernel<<<1024 + 16 + 1, 256>>>(emb, cls, Wp, bp, Ws1, Wv1);
    finish_kernel<<<128 + 2, 256>>>(sel, sidx, bv1, Wv2, bv2, bs1, Ws2, bs2, out);
}